// round 10
// baseline (speedup 1.0000x reference)
#include <cuda_runtime.h>
#include <cuda_bf16.h>
#include <math.h>

#define B_SZ 4
#define T_LEN 1024
#define D_MODEL 128
#define D_STATE 64
#define ED 256
#define DT_RANK 8
#define ROWS (B_SZ * T_LEN)          // 4096
#define EPS 1e-5f
#define LOG2E 1.44269504088896340736f

// ---------------- scratch (device globals; no allocation allowed) -------------
__device__ float g_z[ROWS * D_MODEL];        // z residual
__device__ float g_zn[ROWS * D_MODEL];       // rmsnorm(z)
__device__ float g_xz[ROWS * 2 * ED];        // in_proj output (xs_raw | zg)
__device__ float g_xs[ROWS * ED];            // conv+silu output
__device__ float g_dbc[ROWS * 136];          // x_proj output (dt|B|C)
__device__ float g_yg[ROWS * ED];            // gated scan output
__device__ float g_core[ROWS * D_MODEL];     // out_proj output

// ---------------- helpers ------------------------------------------------------
__device__ __forceinline__ float f2tf32(float x) {
    float r;
    asm("cvt.rna.tf32.f32 %0, %1;" : "=f"(r) : "f"(x));
    return r;
}
__device__ __forceinline__ unsigned fbits(float x) { return __float_as_uint(x); }

// ---------------- kernel 1: z = z_seq + aux@auxW^T + aux_b ; zn = rmsnorm(z) --
__global__ void pre_kernel(const float* __restrict__ z_seq,
                           const float* __restrict__ aux_t,
                           const float* __restrict__ aux_W,
                           const float* __restrict__ aux_b,
                           const float* __restrict__ rms_w) {
    int row = blockIdx.x;                // b*T + t
    int d = threadIdx.x;                 // 0..127
    float a0 = aux_t[row * 3 + 0];
    float a1 = aux_t[row * 3 + 1];
    float a2 = aux_t[row * 3 + 2];
    float z = z_seq[row * D_MODEL + d]
            + a0 * aux_W[d * 3 + 0] + a1 * aux_W[d * 3 + 1] + a2 * aux_W[d * 3 + 2]
            + aux_b[d];
    float s = z * z;
    #pragma unroll
    for (int o = 16; o; o >>= 1) s += __shfl_xor_sync(0xffffffffu, s, o);
    __shared__ float ws[4];
    if ((d & 31) == 0) ws[d >> 5] = s;
    __syncthreads();
    float ms = (ws[0] + ws[1] + ws[2] + ws[3]) * (1.0f / 128.0f);
    float zn = z * rsqrtf(ms + EPS) * rms_w[d];
    g_z[row * D_MODEL + d] = z;
    g_zn[row * D_MODEL + d] = zn;
}

// ---------------- tf32 tensor-core NT GEMM, double buffered --------------------
// C[m][n] = sum_k A[m][k] * B[n][k].
// BM=32, BN=64, BK=16, 128 threads (4 warps as 2m x 2n), warp tile 16x32.
// Small CTAs -> large grids (1024/384/256) and ~10 resident CTAs/SM so BAR/LDS
// latency is hidden. K-permuted smem layout: every mma fragment is one LDS.64.
#define BM 32
#define BN 64
#define BK 16
__global__ __launch_bounds__(128) void gemm_tf32_nt(
    const float* __restrict__ A, const float* __restrict__ B,
    float* __restrict__ C, int M, int N, int K) {
    __shared__ float As[2][BM][BK + 2];
    __shared__ float Bs[2][BN][BK + 2];
    const int tid  = threadIdx.x;
    const int lane = tid & 31;
    const int w    = tid >> 5;
    const int wm   = w & 1;            // 2 m groups (16 rows each)
    const int wn   = w >> 1;           // 2 n groups (32 cols each)
    const int g    = lane >> 2;        // 0..7
    const int tig  = lane & 3;         // 0..3
    const int m0   = blockIdx.y * BM;
    const int n0   = blockIdx.x * BN;

    const int lr  = tid >> 2;          // load row 0..31
    const int lk4 = tid & 3;           // float4 index over BK
    const int kbase = (lk4 >> 1) * 8 + (lk4 & 1);

    const float* Aptr = A + (size_t)(m0 + lr) * K + lk4 * 4;
    const bool   bok0 = (n0 + lr) < N;
    const bool   bok1 = (n0 + lr + 32) < N;
    const float* Bptr0 = B + (size_t)(bok0 ? (n0 + lr) : 0) * K + lk4 * 4;
    const float* Bptr1 = B + (size_t)(bok1 ? (n0 + lr + 32) : 0) * K + lk4 * 4;

    // prologue: tile 0
    float4 va  = *(const float4*)Aptr;
    float4 vb0 = bok0 ? *(const float4*)Bptr0 : make_float4(0.f, 0.f, 0.f, 0.f);
    float4 vb1 = bok1 ? *(const float4*)Bptr1 : make_float4(0.f, 0.f, 0.f, 0.f);
    {
        float* da = &As[0][lr][kbase];
        da[0] = f2tf32(va.x); da[2] = f2tf32(va.y);
        da[4] = f2tf32(va.z); da[6] = f2tf32(va.w);
        float* d0 = &Bs[0][lr][kbase];
        d0[0] = f2tf32(vb0.x); d0[2] = f2tf32(vb0.y);
        d0[4] = f2tf32(vb0.z); d0[6] = f2tf32(vb0.w);
        float* d1 = &Bs[0][lr + 32][kbase];
        d1[0] = f2tf32(vb1.x); d1[2] = f2tf32(vb1.y);
        d1[4] = f2tf32(vb1.z); d1[6] = f2tf32(vb1.w);
    }
    __syncthreads();

    float c[4][4] = {};
    const int nIter = K / BK;
    for (int i = 0; i < nIter; ++i) {
        const int cur = i & 1;
        // prefetch next tile (LDG early; latency covered by MMA below)
        if (i + 1 < nIter) {
            va  = *(const float4*)(Aptr + (i + 1) * BK);
            vb0 = bok0 ? *(const float4*)(Bptr0 + (i + 1) * BK)
                       : make_float4(0.f, 0.f, 0.f, 0.f);
            vb1 = bok1 ? *(const float4*)(Bptr1 + (i + 1) * BK)
                       : make_float4(0.f, 0.f, 0.f, 0.f);
        }
        #pragma unroll
        for (int kb = 0; kb < 2; ++kb) {
            unsigned a[4], bf[4][2];
            {
                int mr = wm * 16;
                float2 lo = *(const float2*)&As[cur][mr + g][kb * 8 + 2 * tig];
                float2 hi = *(const float2*)&As[cur][mr + g + 8][kb * 8 + 2 * tig];
                a[0] = fbits(lo.x); a[2] = fbits(lo.y);
                a[1] = fbits(hi.x); a[3] = fbits(hi.y);
            }
            #pragma unroll
            for (int nt = 0; nt < 4; ++nt) {
                int nr = wn * 32 + nt * 8;
                float2 bv = *(const float2*)&Bs[cur][nr + g][kb * 8 + 2 * tig];
                bf[nt][0] = fbits(bv.x); bf[nt][1] = fbits(bv.y);
            }
            #pragma unroll
            for (int nt = 0; nt < 4; ++nt)
                asm volatile(
                    "mma.sync.aligned.m16n8k8.row.col.f32.tf32.tf32.f32 "
                    "{%0,%1,%2,%3}, {%4,%5,%6,%7}, {%8,%9}, {%0,%1,%2,%3};"
                    : "+f"(c[nt][0]), "+f"(c[nt][1]),
                      "+f"(c[nt][2]), "+f"(c[nt][3])
                    : "r"(a[0]), "r"(a[1]), "r"(a[2]), "r"(a[3]),
                      "r"(bf[nt][0]), "r"(bf[nt][1]));
        }
        // stage next tile into the alternate buffer
        if (i + 1 < nIter) {
            float* da = &As[cur ^ 1][lr][kbase];
            da[0] = f2tf32(va.x); da[2] = f2tf32(va.y);
            da[4] = f2tf32(va.z); da[6] = f2tf32(va.w);
            float* d0 = &Bs[cur ^ 1][lr][kbase];
            d0[0] = f2tf32(vb0.x); d0[2] = f2tf32(vb0.y);
            d0[4] = f2tf32(vb0.z); d0[6] = f2tf32(vb0.w);
            float* d1 = &Bs[cur ^ 1][lr + 32][kbase];
            d1[0] = f2tf32(vb1.x); d1[2] = f2tf32(vb1.y);
            d1[4] = f2tf32(vb1.z); d1[6] = f2tf32(vb1.w);
        }
        __syncthreads();
    }
    {
        int r = m0 + wm * 16 + g;
        #pragma unroll
        for (int nt = 0; nt < 4; ++nt) {
            int cb = n0 + wn * 32 + nt * 8 + 2 * tig;
            if (cb < N) {
                *(float2*)&C[(size_t)r * N + cb] = make_float2(c[nt][0], c[nt][1]);
                *(float2*)&C[(size_t)(r + 8) * N + cb] = make_float2(c[nt][2], c[nt][3]);
            }
        }
    }
}

// ---------------- kernel 3: depthwise causal conv(4) + bias + silu ------------
__global__ void conv_kernel(const float* __restrict__ conv_W,
                            const float* __restrict__ conv_b) {
    int idx = blockIdx.x * blockDim.x + threadIdx.x;   // over ROWS*ED
    if (idx >= ROWS * ED) return;
    int e = idx & (ED - 1);
    int bt = idx >> 8;
    int t = bt & (T_LEN - 1);
    int b = bt >> 10;
    float acc = conv_b[e];
    #pragma unroll
    for (int k = 0; k < 4; ++k) {
        int tt = t - 3 + k;
        if (tt >= 0)
            acc = fmaf(g_xz[(size_t)(b * T_LEN + tt) * (2 * ED) + e], conv_W[e * 4 + k], acc);
    }
    float s = acc / (1.0f + __expf(-acc));   // silu
    g_xs[idx] = s;
}

// ---------------- kernel 5: selective scan + fused delta + fused gate ----------
// CTA: (e-tile of 8, b). Warp w owns e=e0+w; lane owns states {2l, 2l+1}.
// Tile-load phase also computes delta = softplus(dt@dtW + dt_b) in-place
// (eliminates the old 64-CTA delta kernel and 32 MB of intermediate traffic).
// Per t: one shfl16, lanes<16 store partials to smem; the 16-way reduction is
// merged into the gate epilogue pass (LDS.128 x4 per output element).
#define CT 32
__global__ __launch_bounds__(256) void scan_kernel(const float* __restrict__ A_log,
                                                   const float* __restrict__ D_param,
                                                   const float* __restrict__ dt_W,
                                                   const float* __restrict__ dt_b) {
    __shared__ float sB[CT][64];                  // 8 KB
    __shared__ float sC[CT][64];                  // 8 KB
    __shared__ float sDT[CT][8];                  // 1 KB
    __shared__ float sD[8][CT];                   // 1 KB
    __shared__ float sDX[8][CT];                  // 1 KB
    __shared__ float sXS[8][CT];                  // 1 KB
    __shared__ __align__(16) float sP[CT][8][20]; // 20.5 KB (16 used, pad to 20)
    __shared__ float sDp[8];
    int b = blockIdx.y;
    int e0 = blockIdx.x * 8;
    int tid = threadIdx.x;
    int w = tid >> 5, lane = tid & 31;
    int e = e0 + w;
    if (tid < 8) sDp[tid] = D_param[e0 + tid];
    float k0 = -__expf(A_log[e * D_STATE + 2 * lane])     * LOG2E;
    float k1 = -__expf(A_log[e * D_STATE + 2 * lane + 1]) * LOG2E;
    float dtw[8];
    #pragma unroll
    for (int r = 0; r < 8; ++r) dtw[r] = dt_W[e * 8 + r];
    const float dtb = dt_b[e];
    float h0 = 0.f, h1 = 0.f;
    const int jj = tid & 7, tt = tid >> 3;        // reduce-pass mapping
    for (int t0 = 0; t0 < T_LEN; t0 += CT) {
        // stage dt|B|C rows (136 floats = 34 float4 each)
        for (int idx = tid; idx < CT * 34; idx += 256) {
            int r = idx / 34, c4 = idx - r * 34;
            float4 v = *(const float4*)&g_dbc[(size_t)(b * T_LEN + t0 + r) * 136 + c4 * 4];
            if (c4 < 2)       *(float4*)&sDT[r][c4 * 4] = v;
            else if (c4 < 18) *(float4*)&sB[r][(c4 - 2) * 4] = v;
            else              *(float4*)&sC[r][(c4 - 18) * 4] = v;
        }
        __syncthreads();
        // fused delta: (e=w's e, t=lane)
        {
            float acc = dtb;
            #pragma unroll
            for (int r = 0; r < 8; ++r) acc = fmaf(sDT[lane][r], dtw[r], acc);
            float dl = (acc > 20.0f) ? acc : __logf(1.0f + __expf(acc));
            float xs = g_xs[(size_t)(b * T_LEN + t0 + lane) * ED + e];
            sD[w][lane]  = dl;
            sXS[w][lane] = xs;
            sDX[w][lane] = dl * xs;
        }
        __syncwarp();
        #pragma unroll 8
        for (int t = 0; t < CT; ++t) {
            float d  = sD[w][t];
            float dx = sDX[w][t];
            float a0 = exp2f(d * k0);
            float a1 = exp2f(d * k1);
            float2 Bv = *(const float2*)&sB[t][2 * lane];
            float2 Cv = *(const float2*)&sC[t][2 * lane];
            h0 = fmaf(a0, h0, dx * Bv.x);
            h1 = fmaf(a1, h1, dx * Bv.y);
            float p = h0 * Cv.x + h1 * Cv.y;
            p += __shfl_xor_sync(0xffffffffu, p, 16);
            if (lane < 16) sP[t][w][lane] = p;
        }
        __syncthreads();
        // reduce + gate: one (tt, jj) output element per thread
        {
            const float4* pp = (const float4*)&sP[tt][jj][0];
            float4 q0 = pp[0], q1 = pp[1], q2 = pp[2], q3 = pp[3];
            float y = ((q0.x + q0.y) + (q0.z + q0.w))
                    + ((q1.x + q1.y) + (q1.z + q1.w))
                    + ((q2.x + q2.y) + (q2.z + q2.w))
                    + ((q3.x + q3.y) + (q3.z + q3.w));
            size_t row = (size_t)(b * T_LEN + t0 + tt);
            float xs = sXS[jj][tt];
            float zg = g_xz[row * (2 * ED) + ED + e0 + jj];
            float sg = zg / (1.0f + __expf(-zg));
            g_yg[row * ED + e0 + jj] = (y + sDp[jj] * xs) * sg;
        }
        // no extra sync: next load phase writes sB/sC/sDT (disjoint from sP/sXS);
        // sD/sDX/sXS are rewritten only after the next post-load __syncthreads.
    }
}

// ---------------- kernel 9: r = core + 2z; LayerNorm ---------------------------
__global__ void ln_kernel(const float* __restrict__ ln_w,
                          const float* __restrict__ ln_b,
                          float* __restrict__ out) {
    int row = blockIdx.x;
    int d = threadIdx.x;
    float r = g_core[row * D_MODEL + d] + 2.0f * g_z[row * D_MODEL + d];
    float s = r;
    #pragma unroll
    for (int o = 16; o; o >>= 1) s += __shfl_xor_sync(0xffffffffu, s, o);
    __shared__ float a4[4], b4[4];
    if ((d & 31) == 0) a4[d >> 5] = s;
    __syncthreads();
    float mu = (a4[0] + a4[1] + a4[2] + a4[3]) * (1.0f / 128.0f);
    float c = r - mu;
    float q = c * c;
    #pragma unroll
    for (int o = 16; o; o >>= 1) q += __shfl_xor_sync(0xffffffffu, q, o);
    if ((d & 31) == 0) b4[d >> 5] = q;
    __syncthreads();
    float var = (b4[0] + b4[1] + b4[2] + b4[3]) * (1.0f / 128.0f);
    out[row * D_MODEL + d] = c * rsqrtf(var + EPS) * ln_w[d] + ln_b[d];
}

// ---------------- launch --------------------------------------------------------
extern "C" void kernel_launch(void* const* d_in, const int* in_sizes, int n_in,
                              void* d_out, int out_size) {
    const float* z_seq      = (const float*)d_in[0];
    const float* aux_tensor = (const float*)d_in[1];
    const float* aux_W      = (const float*)d_in[2];
    const float* aux_b      = (const float*)d_in[3];
    const float* ln_w       = (const float*)d_in[4];
    const float* ln_b       = (const float*)d_in[5];
    const float* rms_w      = (const float*)d_in[6];
    const float* in_proj_W  = (const float*)d_in[7];
    const float* conv_W     = (const float*)d_in[8];
    const float* conv_b     = (const float*)d_in[9];
    const float* x_proj_W   = (const float*)d_in[10];
    const float* dt_W       = (const float*)d_in[11];
    const float* dt_b       = (const float*)d_in[12];
    const float* A_log      = (const float*)d_in[13];
    const float* D_param    = (const float*)d_in[14];
    const float* out_proj_W = (const float*)d_in[15];
    float* out = (float*)d_out;

    float *p_zn, *p_xz, *p_xs, *p_dbc, *p_yg, *p_core;
    cudaGetSymbolAddress((void**)&p_zn,   g_zn);
    cudaGetSymbolAddress((void**)&p_xz,   g_xz);
    cudaGetSymbolAddress((void**)&p_xs,   g_xs);
    cudaGetSymbolAddress((void**)&p_dbc,  g_dbc);
    cudaGetSymbolAddress((void**)&p_yg,   g_yg);
    cudaGetSymbolAddress((void**)&p_core, g_core);

    // 1. pre: z + rmsnorm
    pre_kernel<<<ROWS, 128>>>(z_seq, aux_tensor, aux_W, aux_b, rms_w);

    // 2. in_proj: xz = zn @ in_proj_W^T   (4096 x 512, K=128)  [tf32 MMA]
    gemm_tf32_nt<<<dim3(512 / BN, ROWS / BM), 128>>>(p_zn, in_proj_W, p_xz,
                                                     ROWS, 2 * ED, D_MODEL);

    // 3. depthwise conv + silu
    conv_kernel<<<(ROWS * ED) / 256, 256>>>(conv_W, conv_b);

    // 4. x_proj: dbc = xs @ x_proj_W^T    (4096 x 136, K=256)  [tf32 MMA]
    gemm_tf32_nt<<<dim3(3, ROWS / BM), 128>>>(p_xs, x_proj_W, p_dbc,
                                              ROWS, 136, ED);

    // 5. selective scan + fused delta + fused gate
    scan_kernel<<<dim3(ED / 8, B_SZ), 256>>>(A_log, D_param, dt_W, dt_b);

    // 6. out_proj: core = yg @ out_proj_W^T   (4096 x 128, K=256)  [tf32 MMA]
    gemm_tf32_nt<<<dim3(2, ROWS / BM), 128>>>(p_yg, out_proj_W, p_core,
                                              ROWS, D_MODEL, ED);

    // 7. residual (core + 2z) + LayerNorm
    ln_kernel<<<ROWS, 128>>>(ln_w, ln_b, out);
}

// round 11
// speedup vs baseline: 1.0010x; 1.0010x over previous
#include <cuda_runtime.h>
#include <cuda_bf16.h>
#include <math.h>

#define B_SZ 4
#define T_LEN 1024
#define D_MODEL 128
#define D_STATE 64
#define ED 256
#define DT_RANK 8
#define ROWS (B_SZ * T_LEN)          // 4096
#define EPS 1e-5f
#define LOG2E 1.44269504088896340736f

// ---------------- scratch (device globals; no allocation allowed) -------------
__device__ float g_z[ROWS * D_MODEL];        // z residual
__device__ float g_zn[ROWS * D_MODEL];       // rmsnorm(z)
__device__ float g_xz[ROWS * 2 * ED];        // in_proj output (xs_raw | zg)
__device__ float g_xs[ROWS * ED];            // conv+silu output
__device__ float g_dbc[ROWS * 136];          // x_proj output (dt|B|C)
__device__ float g_yg[ROWS * ED];            // gated scan output
__device__ float g_core[ROWS * D_MODEL];     // out_proj output

// ---------------- helpers ------------------------------------------------------
__device__ __forceinline__ float f2tf32(float x) {
    float r;
    asm("cvt.rna.tf32.f32 %0, %1;" : "=f"(r) : "f"(x));
    return r;
}
__device__ __forceinline__ unsigned fbits(float x) { return __float_as_uint(x); }

// ---------------- kernel 1: z = z_seq + aux@auxW^T + aux_b ; zn = rmsnorm(z) --
__global__ void pre_kernel(const float* __restrict__ z_seq,
                           const float* __restrict__ aux_t,
                           const float* __restrict__ aux_W,
                           const float* __restrict__ aux_b,
                           const float* __restrict__ rms_w) {
    int row = blockIdx.x;                // b*T + t
    int d = threadIdx.x;                 // 0..127
    float a0 = aux_t[row * 3 + 0];
    float a1 = aux_t[row * 3 + 1];
    float a2 = aux_t[row * 3 + 2];
    float z = z_seq[row * D_MODEL + d]
            + a0 * aux_W[d * 3 + 0] + a1 * aux_W[d * 3 + 1] + a2 * aux_W[d * 3 + 2]
            + aux_b[d];
    float s = z * z;
    #pragma unroll
    for (int o = 16; o; o >>= 1) s += __shfl_xor_sync(0xffffffffu, s, o);
    __shared__ float ws[4];
    if ((d & 31) == 0) ws[d >> 5] = s;
    __syncthreads();
    float ms = (ws[0] + ws[1] + ws[2] + ws[3]) * (1.0f / 128.0f);
    float zn = z * rsqrtf(ms + EPS) * rms_w[d];
    g_z[row * D_MODEL + d] = z;
    g_zn[row * D_MODEL + d] = zn;
}

// ---------------- tf32 tensor-core NT GEMM, double buffered --------------------
// C[m][n] = sum_k A[m][k] * B[n][k].
// BM=32, BN=64, BK=16, 128 threads (4 warps as 2m x 2n), warp tile 16x32.
#define BM 32
#define BN 64
#define BK 16
__global__ __launch_bounds__(128) void gemm_tf32_nt(
    const float* __restrict__ A, const float* __restrict__ B,
    float* __restrict__ C, int M, int N, int K) {
    __shared__ float As[2][BM][BK + 2];
    __shared__ float Bs[2][BN][BK + 2];
    const int tid  = threadIdx.x;
    const int lane = tid & 31;
    const int w    = tid >> 5;
    const int wm   = w & 1;            // 2 m groups (16 rows each)
    const int wn   = w >> 1;           // 2 n groups (32 cols each)
    const int g    = lane >> 2;        // 0..7
    const int tig  = lane & 3;         // 0..3
    const int m0   = blockIdx.y * BM;
    const int n0   = blockIdx.x * BN;

    const int lr  = tid >> 2;          // load row 0..31
    const int lk4 = tid & 3;           // float4 index over BK
    const int kbase = (lk4 >> 1) * 8 + (lk4 & 1);

    const float* Aptr = A + (size_t)(m0 + lr) * K + lk4 * 4;
    const bool   bok0 = (n0 + lr) < N;
    const bool   bok1 = (n0 + lr + 32) < N;
    const float* Bptr0 = B + (size_t)(bok0 ? (n0 + lr) : 0) * K + lk4 * 4;
    const float* Bptr1 = B + (size_t)(bok1 ? (n0 + lr + 32) : 0) * K + lk4 * 4;

    // prologue: tile 0
    float4 va  = *(const float4*)Aptr;
    float4 vb0 = bok0 ? *(const float4*)Bptr0 : make_float4(0.f, 0.f, 0.f, 0.f);
    float4 vb1 = bok1 ? *(const float4*)Bptr1 : make_float4(0.f, 0.f, 0.f, 0.f);
    {
        float* da = &As[0][lr][kbase];
        da[0] = f2tf32(va.x); da[2] = f2tf32(va.y);
        da[4] = f2tf32(va.z); da[6] = f2tf32(va.w);
        float* d0 = &Bs[0][lr][kbase];
        d0[0] = f2tf32(vb0.x); d0[2] = f2tf32(vb0.y);
        d0[4] = f2tf32(vb0.z); d0[6] = f2tf32(vb0.w);
        float* d1 = &Bs[0][lr + 32][kbase];
        d1[0] = f2tf32(vb1.x); d1[2] = f2tf32(vb1.y);
        d1[4] = f2tf32(vb1.z); d1[6] = f2tf32(vb1.w);
    }
    __syncthreads();

    float c[4][4] = {};
    const int nIter = K / BK;
    for (int i = 0; i < nIter; ++i) {
        const int cur = i & 1;
        // prefetch next tile (LDG early; latency covered by MMA below)
        if (i + 1 < nIter) {
            va  = *(const float4*)(Aptr + (i + 1) * BK);
            vb0 = bok0 ? *(const float4*)(Bptr0 + (i + 1) * BK)
                       : make_float4(0.f, 0.f, 0.f, 0.f);
            vb1 = bok1 ? *(const float4*)(Bptr1 + (i + 1) * BK)
                       : make_float4(0.f, 0.f, 0.f, 0.f);
        }
        #pragma unroll
        for (int kb = 0; kb < 2; ++kb) {
            unsigned a[4], bf[4][2];
            {
                int mr = wm * 16;
                float2 lo = *(const float2*)&As[cur][mr + g][kb * 8 + 2 * tig];
                float2 hi = *(const float2*)&As[cur][mr + g + 8][kb * 8 + 2 * tig];
                a[0] = fbits(lo.x); a[2] = fbits(lo.y);
                a[1] = fbits(hi.x); a[3] = fbits(hi.y);
            }
            #pragma unroll
            for (int nt = 0; nt < 4; ++nt) {
                int nr = wn * 32 + nt * 8;
                float2 bv = *(const float2*)&Bs[cur][nr + g][kb * 8 + 2 * tig];
                bf[nt][0] = fbits(bv.x); bf[nt][1] = fbits(bv.y);
            }
            #pragma unroll
            for (int nt = 0; nt < 4; ++nt)
                asm volatile(
                    "mma.sync.aligned.m16n8k8.row.col.f32.tf32.tf32.f32 "
                    "{%0,%1,%2,%3}, {%4,%5,%6,%7}, {%8,%9}, {%0,%1,%2,%3};"
                    : "+f"(c[nt][0]), "+f"(c[nt][1]),
                      "+f"(c[nt][2]), "+f"(c[nt][3])
                    : "r"(a[0]), "r"(a[1]), "r"(a[2]), "r"(a[3]),
                      "r"(bf[nt][0]), "r"(bf[nt][1]));
        }
        // stage next tile into the alternate buffer
        if (i + 1 < nIter) {
            float* da = &As[cur ^ 1][lr][kbase];
            da[0] = f2tf32(va.x); da[2] = f2tf32(va.y);
            da[4] = f2tf32(va.z); da[6] = f2tf32(va.w);
            float* d0 = &Bs[cur ^ 1][lr][kbase];
            d0[0] = f2tf32(vb0.x); d0[2] = f2tf32(vb0.y);
            d0[4] = f2tf32(vb0.z); d0[6] = f2tf32(vb0.w);
            float* d1 = &Bs[cur ^ 1][lr + 32][kbase];
            d1[0] = f2tf32(vb1.x); d1[2] = f2tf32(vb1.y);
            d1[4] = f2tf32(vb1.z); d1[6] = f2tf32(vb1.w);
        }
        __syncthreads();
    }
    {
        int r = m0 + wm * 16 + g;
        #pragma unroll
        for (int nt = 0; nt < 4; ++nt) {
            int cb = n0 + wn * 32 + nt * 8 + 2 * tig;
            if (cb < N) {
                *(float2*)&C[(size_t)r * N + cb] = make_float2(c[nt][0], c[nt][1]);
                *(float2*)&C[(size_t)(r + 8) * N + cb] = make_float2(c[nt][2], c[nt][3]);
            }
        }
    }
}

// ---------------- kernel 3: depthwise causal conv(4) + bias + silu ------------
__global__ void conv_kernel(const float* __restrict__ conv_W,
                            const float* __restrict__ conv_b) {
    int idx = blockIdx.x * blockDim.x + threadIdx.x;   // over ROWS*ED
    if (idx >= ROWS * ED) return;
    int e = idx & (ED - 1);
    int bt = idx >> 8;
    int t = bt & (T_LEN - 1);
    int b = bt >> 10;
    float acc = conv_b[e];
    #pragma unroll
    for (int k = 0; k < 4; ++k) {
        int tt = t - 3 + k;
        if (tt >= 0)
            acc = fmaf(g_xz[(size_t)(b * T_LEN + tt) * (2 * ED) + e], conv_W[e * 4 + k], acc);
    }
    float s = acc / (1.0f + __expf(-acc));   // silu
    g_xs[idx] = s;
}

// ---------------- kernel 5: selective scan + fused delta + fused gate ----------
// CTA: (e-tile of 8, b). Warp w owns e=e0+w; lane owns states {2l, 2l+1}.
// xs is staged into smem COALESCED in the load phase (fix for R10's stride-1KB
// per-warp gather); delta = softplus(dt@dtW + dt_b) computed from smem.
#define CT 32
__global__ __launch_bounds__(256) void scan_kernel(const float* __restrict__ A_log,
                                                   const float* __restrict__ D_param,
                                                   const float* __restrict__ dt_W,
                                                   const float* __restrict__ dt_b) {
    __shared__ float sB[CT][64];                  // 8 KB
    __shared__ float sC[CT][64];                  // 8 KB
    __shared__ float sDT[CT][8];                  // 1 KB
    __shared__ float sD[8][CT];                   // 1 KB
    __shared__ float sDX[8][CT];                  // 1 KB
    __shared__ float sXS[8][CT];                  // 1 KB
    __shared__ __align__(16) float sP[CT][8][20]; // 20.5 KB (16 used, pad to 20)
    __shared__ float sDp[8];
    int b = blockIdx.y;
    int e0 = blockIdx.x * 8;
    int tid = threadIdx.x;
    int w = tid >> 5, lane = tid & 31;
    int e = e0 + w;
    if (tid < 8) sDp[tid] = D_param[e0 + tid];
    float k0 = -__expf(A_log[e * D_STATE + 2 * lane])     * LOG2E;
    float k1 = -__expf(A_log[e * D_STATE + 2 * lane + 1]) * LOG2E;
    float dtw[8];
    #pragma unroll
    for (int r = 0; r < 8; ++r) dtw[r] = dt_W[e * 8 + r];
    const float dtb = dt_b[e];
    float h0 = 0.f, h1 = 0.f;
    const int jj = tid & 7, tt = tid >> 3;        // coalesced (t,e) mapping
    for (int t0 = 0; t0 < T_LEN; t0 += CT) {
        // stage dt|B|C rows (136 floats = 34 float4 each)
        for (int idx = tid; idx < CT * 34; idx += 256) {
            int r = idx / 34, c4 = idx - r * 34;
            float4 v = *(const float4*)&g_dbc[(size_t)(b * T_LEN + t0 + r) * 136 + c4 * 4];
            if (c4 < 2)       *(float4*)&sDT[r][c4 * 4] = v;
            else if (c4 < 18) *(float4*)&sB[r][(c4 - 2) * 4] = v;
            else              *(float4*)&sC[r][(c4 - 18) * 4] = v;
        }
        // stage xs coalesced: thread (tt, jj) -> 8 consecutive floats per row
        sXS[jj][tt] = g_xs[(size_t)(b * T_LEN + t0 + tt) * ED + e0 + jj];
        __syncthreads();
        // fused delta: (e = w's e, t = lane), xs from smem
        {
            float acc = dtb;
            #pragma unroll
            for (int r = 0; r < 8; ++r) acc = fmaf(sDT[lane][r], dtw[r], acc);
            float dl = (acc > 20.0f) ? acc : __logf(1.0f + __expf(acc));
            sD[w][lane]  = dl;
            sDX[w][lane] = dl * sXS[w][lane];
        }
        __syncwarp();
        #pragma unroll 8
        for (int t = 0; t < CT; ++t) {
            float d  = sD[w][t];
            float dx = sDX[w][t];
            float a0 = exp2f(d * k0);
            float a1 = exp2f(d * k1);
            float2 Bv = *(const float2*)&sB[t][2 * lane];
            float2 Cv = *(const float2*)&sC[t][2 * lane];
            h0 = fmaf(a0, h0, dx * Bv.x);
            h1 = fmaf(a1, h1, dx * Bv.y);
            float p = h0 * Cv.x + h1 * Cv.y;
            p += __shfl_xor_sync(0xffffffffu, p, 16);
            if (lane < 16) sP[t][w][lane] = p;
        }
        __syncthreads();
        // reduce + gate: one (tt, jj) output element per thread
        {
            const float4* pp = (const float4*)&sP[tt][jj][0];
            float4 q0 = pp[0], q1 = pp[1], q2 = pp[2], q3 = pp[3];
            float y = ((q0.x + q0.y) + (q0.z + q0.w))
                    + ((q1.x + q1.y) + (q1.z + q1.w))
                    + ((q2.x + q2.y) + (q2.z + q2.w))
                    + ((q3.x + q3.y) + (q3.z + q3.w));
            size_t row = (size_t)(b * T_LEN + t0 + tt);
            float xs = sXS[jj][tt];
            float zg = g_xz[row * (2 * ED) + ED + e0 + jj];
            float sg = zg / (1.0f + __expf(-zg));
            g_yg[row * ED + e0 + jj] = (y + sDp[jj] * xs) * sg;
        }
        // load phase of the next tile rewrites sXS (read by this epilogue) and
        // sB/sC/sDT: must fence before looping.
        __syncthreads();
    }
}

// ---------------- kernel 9: r = core + 2z; LayerNorm ---------------------------
__global__ void ln_kernel(const float* __restrict__ ln_w,
                          const float* __restrict__ ln_b,
                          float* __restrict__ out) {
    int row = blockIdx.x;
    int d = threadIdx.x;
    float r = g_core[row * D_MODEL + d] + 2.0f * g_z[row * D_MODEL + d];
    float s = r;
    #pragma unroll
    for (int o = 16; o; o >>= 1) s += __shfl_xor_sync(0xffffffffu, s, o);
    __shared__ float a4[4], b4[4];
    if ((d & 31) == 0) a4[d >> 5] = s;
    __syncthreads();
    float mu = (a4[0] + a4[1] + a4[2] + a4[3]) * (1.0f / 128.0f);
    float c = r - mu;
    float q = c * c;
    #pragma unroll
    for (int o = 16; o; o >>= 1) q += __shfl_xor_sync(0xffffffffu, q, o);
    if ((d & 31) == 0) b4[d >> 5] = q;
    __syncthreads();
    float var = (b4[0] + b4[1] + b4[2] + b4[3]) * (1.0f / 128.0f);
    out[row * D_MODEL + d] = c * rsqrtf(var + EPS) * ln_w[d] + ln_b[d];
}

// ---------------- launch --------------------------------------------------------
extern "C" void kernel_launch(void* const* d_in, const int* in_sizes, int n_in,
                              void* d_out, int out_size) {
    const float* z_seq      = (const float*)d_in[0];
    const float* aux_tensor = (const float*)d_in[1];
    const float* aux_W      = (const float*)d_in[2];
    const float* aux_b      = (const float*)d_in[3];
    const float* ln_w       = (const float*)d_in[4];
    const float* ln_b       = (const float*)d_in[5];
    const float* rms_w      = (const float*)d_in[6];
    const float* in_proj_W  = (const float*)d_in[7];
    const float* conv_W     = (const float*)d_in[8];
    const float* conv_b     = (const float*)d_in[9];
    const float* x_proj_W   = (const float*)d_in[10];
    const float* dt_W       = (const float*)d_in[11];
    const float* dt_b       = (const float*)d_in[12];
    const float* A_log      = (const float*)d_in[13];
    const float* D_param    = (const float*)d_in[14];
    const float* out_proj_W = (const float*)d_in[15];
    float* out = (float*)d_out;

    float *p_zn, *p_xz, *p_xs, *p_dbc, *p_yg, *p_core;
    cudaGetSymbolAddress((void**)&p_zn,   g_zn);
    cudaGetSymbolAddress((void**)&p_xz,   g_xz);
    cudaGetSymbolAddress((void**)&p_xs,   g_xs);
    cudaGetSymbolAddress((void**)&p_dbc,  g_dbc);
    cudaGetSymbolAddress((void**)&p_yg,   g_yg);
    cudaGetSymbolAddress((void**)&p_core, g_core);

    // 1. pre: z + rmsnorm
    pre_kernel<<<ROWS, 128>>>(z_seq, aux_tensor, aux_W, aux_b, rms_w);

    // 2. in_proj: xz = zn @ in_proj_W^T   (4096 x 512, K=128)  [tf32 MMA]
    gemm_tf32_nt<<<dim3(512 / BN, ROWS / BM), 128>>>(p_zn, in_proj_W, p_xz,
                                                     ROWS, 2 * ED, D_MODEL);

    // 3. depthwise conv + silu
    conv_kernel<<<(ROWS * ED) / 256, 256>>>(conv_W, conv_b);

    // 4. x_proj: dbc = xs @ x_proj_W^T    (4096 x 136, K=256)  [tf32 MMA]
    gemm_tf32_nt<<<dim3(3, ROWS / BM), 128>>>(p_xs, x_proj_W, p_dbc,
                                              ROWS, 136, ED);

    // 5. selective scan + fused delta + fused gate
    scan_kernel<<<dim3(ED / 8, B_SZ), 256>>>(A_log, D_param, dt_W, dt_b);

    // 6. out_proj: core = yg @ out_proj_W^T   (4096 x 128, K=256)  [tf32 MMA]
    gemm_tf32_nt<<<dim3(2, ROWS / BM), 128>>>(p_yg, out_proj_W, p_core,
                                              ROWS, D_MODEL, ED);

    // 7. residual (core + 2z) + LayerNorm
    ln_kernel<<<ROWS, 128>>>(ln_w, ln_b, out);
}

// round 12
// speedup vs baseline: 1.2290x; 1.2277x over previous
#include <cuda_runtime.h>
#include <cuda_bf16.h>
#include <math.h>

#define B_SZ 4
#define T_LEN 1024
#define D_MODEL 128
#define D_STATE 64
#define ED 256
#define DT_RANK 8
#define ROWS (B_SZ * T_LEN)          // 4096
#define EPS 1e-5f
#define LOG2E 1.44269504088896340736f

// ---------------- scratch (device globals; no allocation allowed) -------------
__device__ float g_z[ROWS * D_MODEL];        // z residual
__device__ float g_zn[ROWS * D_MODEL];       // rmsnorm(z)
__device__ float g_xz[ROWS * 2 * ED];        // in_proj output (xs_raw | zg)
__device__ float g_xs[ROWS * ED];            // conv+silu output
__device__ float g_dbc[ROWS * 136];          // x_proj output (dt|B|C)
__device__ float g_yg[ROWS * ED];            // gated scan output
__device__ float g_core[ROWS * D_MODEL];     // out_proj output

// ---------------- helpers ------------------------------------------------------
__device__ __forceinline__ float f2tf32(float x) {
    float r;
    asm("cvt.rna.tf32.f32 %0, %1;" : "=f"(r) : "f"(x));
    return r;
}
__device__ __forceinline__ unsigned fbits(float x) { return __float_as_uint(x); }
__device__ __forceinline__ float ex2(float x) {       // single MUFU.EX2
    float y;
    asm("ex2.approx.f32 %0, %1;" : "=f"(y) : "f"(x));
    return y;
}

// ---------------- kernel 1: z = z_seq + aux@auxW^T + aux_b ; zn = rmsnorm(z) --
__global__ void pre_kernel(const float* __restrict__ z_seq,
                           const float* __restrict__ aux_t,
                           const float* __restrict__ aux_W,
                           const float* __restrict__ aux_b,
                           const float* __restrict__ rms_w) {
    int row = blockIdx.x;                // b*T + t
    int d = threadIdx.x;                 // 0..127
    float a0 = aux_t[row * 3 + 0];
    float a1 = aux_t[row * 3 + 1];
    float a2 = aux_t[row * 3 + 2];
    float z = z_seq[row * D_MODEL + d]
            + a0 * aux_W[d * 3 + 0] + a1 * aux_W[d * 3 + 1] + a2 * aux_W[d * 3 + 2]
            + aux_b[d];
    float s = z * z;
    #pragma unroll
    for (int o = 16; o; o >>= 1) s += __shfl_xor_sync(0xffffffffu, s, o);
    __shared__ float ws[4];
    if ((d & 31) == 0) ws[d >> 5] = s;
    __syncthreads();
    float ms = (ws[0] + ws[1] + ws[2] + ws[3]) * (1.0f / 128.0f);
    float zn = z * rsqrtf(ms + EPS) * rms_w[d];
    g_z[row * D_MODEL + d] = z;
    g_zn[row * D_MODEL + d] = zn;
}

// ---------------- tf32 tensor-core NT GEMM, double buffered --------------------
// C[m][n] = sum_k A[m][k] * B[n][k].
// BM=32, BN=64, BK=16, 128 threads (4 warps as 2m x 2n), warp tile 16x32.
#define BM 32
#define BN 64
#define BK 16
__global__ __launch_bounds__(128) void gemm_tf32_nt(
    const float* __restrict__ A, const float* __restrict__ B,
    float* __restrict__ C, int M, int N, int K) {
    __shared__ float As[2][BM][BK + 2];
    __shared__ float Bs[2][BN][BK + 2];
    const int tid  = threadIdx.x;
    const int lane = tid & 31;
    const int w    = tid >> 5;
    const int wm   = w & 1;            // 2 m groups (16 rows each)
    const int wn   = w >> 1;           // 2 n groups (32 cols each)
    const int g    = lane >> 2;        // 0..7
    const int tig  = lane & 3;         // 0..3
    const int m0   = blockIdx.y * BM;
    const int n0   = blockIdx.x * BN;

    const int lr  = tid >> 2;          // load row 0..31
    const int lk4 = tid & 3;           // float4 index over BK
    const int kbase = (lk4 >> 1) * 8 + (lk4 & 1);

    const float* Aptr = A + (size_t)(m0 + lr) * K + lk4 * 4;
    const bool   bok0 = (n0 + lr) < N;
    const bool   bok1 = (n0 + lr + 32) < N;
    const float* Bptr0 = B + (size_t)(bok0 ? (n0 + lr) : 0) * K + lk4 * 4;
    const float* Bptr1 = B + (size_t)(bok1 ? (n0 + lr + 32) : 0) * K + lk4 * 4;

    // prologue: tile 0
    float4 va  = *(const float4*)Aptr;
    float4 vb0 = bok0 ? *(const float4*)Bptr0 : make_float4(0.f, 0.f, 0.f, 0.f);
    float4 vb1 = bok1 ? *(const float4*)Bptr1 : make_float4(0.f, 0.f, 0.f, 0.f);
    {
        float* da = &As[0][lr][kbase];
        da[0] = f2tf32(va.x); da[2] = f2tf32(va.y);
        da[4] = f2tf32(va.z); da[6] = f2tf32(va.w);
        float* d0 = &Bs[0][lr][kbase];
        d0[0] = f2tf32(vb0.x); d0[2] = f2tf32(vb0.y);
        d0[4] = f2tf32(vb0.z); d0[6] = f2tf32(vb0.w);
        float* d1 = &Bs[0][lr + 32][kbase];
        d1[0] = f2tf32(vb1.x); d1[2] = f2tf32(vb1.y);
        d1[4] = f2tf32(vb1.z); d1[6] = f2tf32(vb1.w);
    }
    __syncthreads();

    float c[4][4] = {};
    const int nIter = K / BK;
    for (int i = 0; i < nIter; ++i) {
        const int cur = i & 1;
        // prefetch next tile (LDG early; latency covered by MMA below)
        if (i + 1 < nIter) {
            va  = *(const float4*)(Aptr + (i + 1) * BK);
            vb0 = bok0 ? *(const float4*)(Bptr0 + (i + 1) * BK)
                       : make_float4(0.f, 0.f, 0.f, 0.f);
            vb1 = bok1 ? *(const float4*)(Bptr1 + (i + 1) * BK)
                       : make_float4(0.f, 0.f, 0.f, 0.f);
        }
        #pragma unroll
        for (int kb = 0; kb < 2; ++kb) {
            unsigned a[4], bf[4][2];
            {
                int mr = wm * 16;
                float2 lo = *(const float2*)&As[cur][mr + g][kb * 8 + 2 * tig];
                float2 hi = *(const float2*)&As[cur][mr + g + 8][kb * 8 + 2 * tig];
                a[0] = fbits(lo.x); a[2] = fbits(lo.y);
                a[1] = fbits(hi.x); a[3] = fbits(hi.y);
            }
            #pragma unroll
            for (int nt = 0; nt < 4; ++nt) {
                int nr = wn * 32 + nt * 8;
                float2 bv = *(const float2*)&Bs[cur][nr + g][kb * 8 + 2 * tig];
                bf[nt][0] = fbits(bv.x); bf[nt][1] = fbits(bv.y);
            }
            #pragma unroll
            for (int nt = 0; nt < 4; ++nt)
                asm volatile(
                    "mma.sync.aligned.m16n8k8.row.col.f32.tf32.tf32.f32 "
                    "{%0,%1,%2,%3}, {%4,%5,%6,%7}, {%8,%9}, {%0,%1,%2,%3};"
                    : "+f"(c[nt][0]), "+f"(c[nt][1]),
                      "+f"(c[nt][2]), "+f"(c[nt][3])
                    : "r"(a[0]), "r"(a[1]), "r"(a[2]), "r"(a[3]),
                      "r"(bf[nt][0]), "r"(bf[nt][1]));
        }
        // stage next tile into the alternate buffer
        if (i + 1 < nIter) {
            float* da = &As[cur ^ 1][lr][kbase];
            da[0] = f2tf32(va.x); da[2] = f2tf32(va.y);
            da[4] = f2tf32(va.z); da[6] = f2tf32(va.w);
            float* d0 = &Bs[cur ^ 1][lr][kbase];
            d0[0] = f2tf32(vb0.x); d0[2] = f2tf32(vb0.y);
            d0[4] = f2tf32(vb0.z); d0[6] = f2tf32(vb0.w);
            float* d1 = &Bs[cur ^ 1][lr + 32][kbase];
            d1[0] = f2tf32(vb1.x); d1[2] = f2tf32(vb1.y);
            d1[4] = f2tf32(vb1.z); d1[6] = f2tf32(vb1.w);
        }
        __syncthreads();
    }
    {
        int r = m0 + wm * 16 + g;
        #pragma unroll
        for (int nt = 0; nt < 4; ++nt) {
            int cb = n0 + wn * 32 + nt * 8 + 2 * tig;
            if (cb < N) {
                *(float2*)&C[(size_t)r * N + cb] = make_float2(c[nt][0], c[nt][1]);
                *(float2*)&C[(size_t)(r + 8) * N + cb] = make_float2(c[nt][2], c[nt][3]);
            }
        }
    }
}

// ---------------- kernel 3: depthwise causal conv(4) + bias + silu ------------
__global__ void conv_kernel(const float* __restrict__ conv_W,
                            const float* __restrict__ conv_b) {
    int idx = blockIdx.x * blockDim.x + threadIdx.x;   // over ROWS*ED
    if (idx >= ROWS * ED) return;
    int e = idx & (ED - 1);
    int bt = idx >> 8;
    int t = bt & (T_LEN - 1);
    int b = bt >> 10;
    float acc = conv_b[e];
    #pragma unroll
    for (int k = 0; k < 4; ++k) {
        int tt = t - 3 + k;
        if (tt >= 0)
            acc = fmaf(g_xz[(size_t)(b * T_LEN + tt) * (2 * ED) + e], conv_W[e * 4 + k], acc);
    }
    float s = acc / (1.0f + __expf(-acc));   // silu
    g_xs[idx] = s;
}

// ---------------- kernel 5: selective scan + fused delta + fused gate ----------
// CTA: (e-tile of 8, b). Warp w owns e=e0+w; lane owns states {2l, 2l+1}.
// Staging uses fixed-trip fully-unrolled loads (all LDGs batched -> high MLP);
// 2 __syncthreads per tile. Delta = softplus(dt@dtW + dt_b) computed in-CTA.
#define CT 32
__global__ __launch_bounds__(256) void scan_kernel(const float* __restrict__ A_log,
                                                   const float* __restrict__ D_param,
                                                   const float* __restrict__ dt_W,
                                                   const float* __restrict__ dt_b) {
    __shared__ float sDT[CT][9];                  // padded: conflict-free dot
    __shared__ float sB[CT][64];                  // 8 KB
    __shared__ float sC[CT][64];                  // 8 KB
    __shared__ float sDD[8][CT][2];               // (delta, delta*xs) interleaved
    __shared__ float sXS[8][CT];                  // xs transposed for delta phase
    __shared__ __align__(16) float sP[CT][8][20]; // partials (16 used, pad 20)
    __shared__ float sDp[8];
    const int b = blockIdx.y;
    const int e0 = blockIdx.x * 8;
    const int tid = threadIdx.x;
    const int w = tid >> 5, lane = tid & 31;
    const int e = e0 + w;
    if (tid < 8) sDp[tid] = D_param[e0 + tid];
    const float k0 = -__expf(A_log[e * D_STATE + 2 * lane])     * LOG2E;
    const float k1 = -__expf(A_log[e * D_STATE + 2 * lane + 1]) * LOG2E;
    float dtw[8];
    #pragma unroll
    for (int r = 0; r < 8; ++r) dtw[r] = dt_W[e * 8 + r];
    const float dtb = dt_b[e];
    float h0 = 0.f, h1 = 0.f;
    const int jj = tid & 7, tt = tid >> 3;        // coalesced (t,e) mapping
    const int lr = tid >> 4, lc = (tid & 15) * 4; // B/C staging coords

    for (int t0 = 0; t0 < T_LEN; t0 += CT) {
        // ---- staging: issue ALL loads first (6 LDGs batched), then stores ----
        const float* base = &g_dbc[(size_t)(b * T_LEN + t0) * 136];
        float4 vb0 = *(const float4*)(base + (size_t)lr * 136 + 8 + lc);
        float4 vb1 = *(const float4*)(base + (size_t)(lr + 16) * 136 + 8 + lc);
        float4 vc0 = *(const float4*)(base + (size_t)lr * 136 + 72 + lc);
        float4 vc1 = *(const float4*)(base + (size_t)(lr + 16) * 136 + 72 + lc);
        float4 vdt = make_float4(0.f, 0.f, 0.f, 0.f);
        if (tid < 64)
            vdt = *(const float4*)(base + (size_t)(tid >> 1) * 136 + (tid & 1) * 4);
        float vxs = g_xs[(size_t)(b * T_LEN + t0 + tt) * ED + e0 + jj];

        *(float4*)&sB[lr][lc]      = vb0;
        *(float4*)&sB[lr + 16][lc] = vb1;
        *(float4*)&sC[lr][lc]      = vc0;
        *(float4*)&sC[lr + 16][lc] = vc1;
        if (tid < 64) {
            int r = tid >> 1, c = (tid & 1) * 4;
            sDT[r][c]     = vdt.x; sDT[r][c + 1] = vdt.y;
            sDT[r][c + 2] = vdt.z; sDT[r][c + 3] = vdt.w;
        }
        sXS[jj][tt] = vxs;
        __syncthreads();                           // sync 1

        // ---- fused delta: (e = w's e, t = lane) ----
        {
            float acc = dtb;
            #pragma unroll
            for (int r = 0; r < 8; ++r) acc = fmaf(sDT[lane][r], dtw[r], acc);
            float dl = (acc > 20.0f) ? acc : __logf(1.0f + __expf(acc));
            sDD[w][lane][0] = dl;
            sDD[w][lane][1] = dl * sXS[w][lane];
        }
        __syncwarp();

        // ---- scan ----
        #pragma unroll 8
        for (int t = 0; t < CT; ++t) {
            float2 dd = *(const float2*)&sDD[w][t][0];
            float a0 = ex2(dd.x * k0);
            float a1 = ex2(dd.x * k1);
            float2 Bv = *(const float2*)&sB[t][2 * lane];
            float2 Cv = *(const float2*)&sC[t][2 * lane];
            h0 = fmaf(a0, h0, dd.y * Bv.x);
            h1 = fmaf(a1, h1, dd.y * Bv.y);
            float p = h0 * Cv.x + h1 * Cv.y;
            p += __shfl_xor_sync(0xffffffffu, p, 16);
            if (lane < 16) sP[t][w][lane] = p;
        }
        __syncthreads();                           // sync 2

        // ---- reduce + gate epilogue: element (tt, jj); xs kept in register ---
        {
            const float4* pp = (const float4*)&sP[tt][jj][0];
            float4 q0 = pp[0], q1 = pp[1], q2 = pp[2], q3 = pp[3];
            float y = ((q0.x + q0.y) + (q0.z + q0.w))
                    + ((q1.x + q1.y) + (q1.z + q1.w))
                    + ((q2.x + q2.y) + (q2.z + q2.w))
                    + ((q3.x + q3.y) + (q3.z + q3.w));
            size_t row = (size_t)(b * T_LEN + t0 + tt);
            float zg = g_xz[row * (2 * ED) + ED + e0 + jj];
            float sg = zg / (1.0f + __expf(-zg));
            g_yg[row * ED + e0 + jj] = (y + sDp[jj] * vxs) * sg;
        }
        // No 3rd sync needed: next tile's writes to sB/sC/sDT/sXS happen only
        // after every thread passes this tile's sync 2; the epilogue reads only
        // sP/registers, and sP is rewritten only after the NEXT sync 1 (all
        // threads must finish this epilogue to reach it). sDD is warp-private.
    }
}

// ---------------- kernel 9: r = core + 2z; LayerNorm ---------------------------
__global__ void ln_kernel(const float* __restrict__ ln_w,
                          const float* __restrict__ ln_b,
                          float* __restrict__ out) {
    int row = blockIdx.x;
    int d = threadIdx.x;
    float r = g_core[row * D_MODEL + d] + 2.0f * g_z[row * D_MODEL + d];
    float s = r;
    #pragma unroll
    for (int o = 16; o; o >>= 1) s += __shfl_xor_sync(0xffffffffu, s, o);
    __shared__ float a4[4], b4[4];
    if ((d & 31) == 0) a4[d >> 5] = s;
    __syncthreads();
    float mu = (a4[0] + a4[1] + a4[2] + a4[3]) * (1.0f / 128.0f);
    float c = r - mu;
    float q = c * c;
    #pragma unroll
    for (int o = 16; o; o >>= 1) q += __shfl_xor_sync(0xffffffffu, q, o);
    if ((d & 31) == 0) b4[d >> 5] = q;
    __syncthreads();
    float var = (b4[0] + b4[1] + b4[2] + b4[3]) * (1.0f / 128.0f);
    out[row * D_MODEL + d] = c * rsqrtf(var + EPS) * ln_w[d] + ln_b[d];
}

// ---------------- launch --------------------------------------------------------
extern "C" void kernel_launch(void* const* d_in, const int* in_sizes, int n_in,
                              void* d_out, int out_size) {
    const float* z_seq      = (const float*)d_in[0];
    const float* aux_tensor = (const float*)d_in[1];
    const float* aux_W      = (const float*)d_in[2];
    const float* aux_b      = (const float*)d_in[3];
    const float* ln_w       = (const float*)d_in[4];
    const float* ln_b       = (const float*)d_in[5];
    const float* rms_w      = (const float*)d_in[6];
    const float* in_proj_W  = (const float*)d_in[7];
    const float* conv_W     = (const float*)d_in[8];
    const float* conv_b     = (const float*)d_in[9];
    const float* x_proj_W   = (const float*)d_in[10];
    const float* dt_W       = (const float*)d_in[11];
    const float* dt_b       = (const float*)d_in[12];
    const float* A_log      = (const float*)d_in[13];
    const float* D_param    = (const float*)d_in[14];
    const float* out_proj_W = (const float*)d_in[15];
    float* out = (float*)d_out;

    float *p_zn, *p_xz, *p_xs, *p_dbc, *p_yg, *p_core;
    cudaGetSymbolAddress((void**)&p_zn,   g_zn);
    cudaGetSymbolAddress((void**)&p_xz,   g_xz);
    cudaGetSymbolAddress((void**)&p_xs,   g_xs);
    cudaGetSymbolAddress((void**)&p_dbc,  g_dbc);
    cudaGetSymbolAddress((void**)&p_yg,   g_yg);
    cudaGetSymbolAddress((void**)&p_core, g_core);

    // 1. pre: z + rmsnorm
    pre_kernel<<<ROWS, 128>>>(z_seq, aux_tensor, aux_W, aux_b, rms_w);

    // 2. in_proj: xz = zn @ in_proj_W^T   (4096 x 512, K=128)  [tf32 MMA]
    gemm_tf32_nt<<<dim3(512 / BN, ROWS / BM), 128>>>(p_zn, in_proj_W, p_xz,
                                                     ROWS, 2 * ED, D_MODEL);

    // 3. depthwise conv + silu
    conv_kernel<<<(ROWS * ED) / 256, 256>>>(conv_W, conv_b);

    // 4. x_proj: dbc = xs @ x_proj_W^T    (4096 x 136, K=256)  [tf32 MMA]
    gemm_tf32_nt<<<dim3(3, ROWS / BM), 128>>>(p_xs, x_proj_W, p_dbc,
                                              ROWS, 136, ED);

    // 5. selective scan + fused delta + fused gate
    scan_kernel<<<dim3(ED / 8, B_SZ), 256>>>(A_log, D_param, dt_W, dt_b);

    // 6. out_proj: core = yg @ out_proj_W^T   (4096 x 128, K=256)  [tf32 MMA]
    gemm_tf32_nt<<<dim3(2, ROWS / BM), 128>>>(p_yg, out_proj_W, p_core,
                                              ROWS, D_MODEL, ED);

    // 7. residual (core + 2z) + LayerNorm
    ln_kernel<<<ROWS, 128>>>(ln_w, ln_b, out);
}